// round 4
// baseline (speedup 1.0000x reference)
#include <cuda_runtime.h>

#define N_NODES 50000
#define N_EDGES 800000
#define NG 256

// ---------------- device scratch (no allocations allowed) ----------------
__device__ int   g_is64;
__device__ float g_PR[N_NODES * 128];   // [P | R] per node, ld=128
__device__ float g_agg[N_NODES * 64];
__device__ float g_H[N_NODES * 64];
__device__ float g_inv[N_NODES];
__device__ int   g_cnt[N_NODES];
__device__ float g_pool[NG * 64];
__device__ int   g_gcnt[NG];
__device__ float g_c0[NG * 64];
__device__ float g_t1[NG * 256];
__device__ float g_t2[NG * 128];
__device__ float g_t3[NG * 64];

// index loader that works for int32 or int64 edge/batch arrays
__device__ __forceinline__ int ld_idx(const void* p, long long i) {
    return g_is64 ? (int)((const long long*)p)[i] : ((const int*)p)[i];
}

// ---------------- dtype detection ----------------
// If data is int64 (values < 50000), every odd int32 word is 0.
// If data is int32, odd words are random edge indices (virtually never all zero).
__global__ void kdetect(const int* ei32) {
    __shared__ int any;
    if (threadIdx.x == 0) any = 0;
    __syncthreads();
    if (ei32[2 * threadIdx.x + 1] != 0) atomicExch(&any, 1);
    __syncthreads();
    if (threadIdx.x == 0) g_is64 = (any == 0) ? 1 : 0;
}

// ---------------- utility ----------------
__global__ void kzero_f(float* p, int n) {
    int i = blockIdx.x * blockDim.x + threadIdx.x;
    if (i < n) p[i] = 0.0f;
}
__global__ void kzero_i(int* p, int n) {
    int i = blockIdx.x * blockDim.x + threadIdx.x;
    if (i < n) p[i] = 0;
}

// ---------------- degree counts ----------------
__global__ void kcount(const void* ei) {
    int e = blockIdx.x * blockDim.x + threadIdx.x;
    if (e < N_EDGES) {
        int d = ld_idx(ei, (long long)N_EDGES + e);
        atomicAdd(&g_cnt[d], 1);
    }
}
__global__ void kinv() {
    int i = blockIdx.x * blockDim.x + threadIdx.x;
    if (i < N_NODES) g_inv[i] = 1.0f / fmaxf((float)g_cnt[i], 1.0f);
}

// ---------------- fused projection GEMM: PR = [X@Wl | X@Wr] ----------------
// block = 128 threads, 4 rows per block; W value reused across 4 rows.
template <int K>
__global__ void gemm_pr(const float* __restrict__ X,
                        const float* __restrict__ Wl,
                        const float* __restrict__ Wr) {
    __shared__ float xs[4][K];
    int row0 = blockIdx.x * 4;
    int tid = threadIdx.x;
#pragma unroll
    for (int r = 0; r < 4; r++)
        for (int k = tid; k < K; k += 128)
            xs[r][k] = X[(long long)(row0 + r) * K + k];
    __syncthreads();

    const float* W = (tid < 64) ? (Wl + tid) : (Wr + (tid - 64));
    float a0 = 0.f, a1 = 0.f, a2 = 0.f, a3 = 0.f;
#pragma unroll 16
    for (int k = 0; k < K; k++) {
        float w = W[k * 64];
        a0 += xs[0][k] * w;
        a1 += xs[1][k] * w;
        a2 += xs[2][k] * w;
        a3 += xs[3][k] * w;
    }
    g_PR[(long long)(row0 + 0) * 128 + tid] = a0;
    g_PR[(long long)(row0 + 1) * 128 + tid] = a1;
    g_PR[(long long)(row0 + 2) * 128 + tid] = a2;
    g_PR[(long long)(row0 + 3) * 128 + tid] = a3;
}

// ---------------- edge scatter: agg[dst] += P[src] ----------------
__global__ void kscatter(const void* ei) {
    int idx = blockIdx.x * blockDim.x + threadIdx.x;
    if (idx >= N_EDGES * 64) return;
    int e = idx >> 6;
    int c = idx & 63;
    int s = ld_idx(ei, e);
    int d = ld_idx(ei, (long long)N_EDGES + e);
    atomicAdd(&g_agg[(long long)d * 64 + c], g_PR[(long long)s * 128 + c]);
}

// ---------------- combine: H = agg*inv + bl + R ----------------
__global__ void kcombine(const float* __restrict__ bl) {
    int idx = blockIdx.x * blockDim.x + threadIdx.x;
    if (idx >= N_NODES * 64) return;
    int i = idx >> 6;
    int c = idx & 63;
    g_H[idx] = g_agg[idx] * g_inv[i] + bl[c] + g_PR[(long long)i * 128 + 64 + c];
}

// ---------------- global mean pool ----------------
__global__ void kpool(const void* batch) {
    int idx = blockIdx.x * blockDim.x + threadIdx.x;
    if (idx >= N_NODES * 64) return;
    int i = idx >> 6;
    int c = idx & 63;
    int g = ld_idx(batch, i);
    atomicAdd(&g_pool[g * 64 + c], g_H[idx]);
    if (c == 0) atomicAdd(&g_gcnt[g], 1);
}
__global__ void kpooldiv() {
    int idx = blockIdx.x * blockDim.x + threadIdx.x;
    if (idx < NG * 64) {
        int g = idx >> 6;
        g_c0[idx] = g_pool[idx] / fmaxf((float)g_gcnt[g], 1.0f);
    }
}

// ---------------- small row GEMM: Y[row] = X[row] @ W + b ----------------
__global__ void gemm_rows(const float* __restrict__ X, const float* __restrict__ W,
                          const float* __restrict__ b, float* __restrict__ Y,
                          int K, int M) {
    extern __shared__ float xs[];
    int row = blockIdx.x;
    int tid = threadIdx.x;
    for (int k = tid; k < K; k += blockDim.x) xs[k] = X[row * K + k];
    __syncthreads();
    if (tid < M) {
        float acc = b[tid];
        for (int k = 0; k < K; k++) acc += xs[k] * W[k * M + tid];
        Y[row * M + tid] = acc;
    }
}

// ---------------- batchnorm (training mode, biased var) + tanh, in place ----------------
// grid = M columns, block = 256 (= NUM_GRAPHS rows)
__global__ void bn_tanh(float* X, const float* __restrict__ g,
                        const float* __restrict__ be, int M) {
    int c = blockIdx.x;
    int r = threadIdx.x;
    __shared__ float red[256];
    __shared__ float stat;
    float v = X[r * M + c];
    red[r] = v;
    __syncthreads();
    for (int s = 128; s > 0; s >>= 1) {
        if (r < s) red[r] += red[r + s];
        __syncthreads();
    }
    if (r == 0) stat = red[0] * (1.0f / 256.0f);
    __syncthreads();
    float mean = stat;
    float d = v - mean;
    __syncthreads();
    red[r] = d * d;
    __syncthreads();
    for (int s = 128; s > 0; s >>= 1) {
        if (r < s) red[r] += red[r + s];
        __syncthreads();
    }
    if (r == 0) stat = rsqrtf(red[0] * (1.0f / 256.0f) + 1e-5f);
    __syncthreads();
    X[r * M + c] = tanhf(d * stat * g[c] + be[c]);
}

// ---------------- host launch ----------------
extern "C" void kernel_launch(void* const* d_in, const int* in_sizes, int n_in,
                              void* d_out, int out_size) {
    const float* x      = (const float*)d_in[0];
    const void*  ei     = d_in[1];
    const void*  batch  = d_in[2];
    const float* W1l    = (const float*)d_in[3];
    const float* b1l    = (const float*)d_in[4];
    const float* W1r    = (const float*)d_in[5];
    const float* W2l    = (const float*)d_in[6];
    const float* b2l    = (const float*)d_in[7];
    const float* W2r    = (const float*)d_in[8];
    const float* W3l    = (const float*)d_in[9];
    const float* b3l    = (const float*)d_in[10];
    const float* W3r    = (const float*)d_in[11];
    const float* lin1_w = (const float*)d_in[12];
    const float* lin1_b = (const float*)d_in[13];
    const float* g1     = (const float*)d_in[14];
    const float* be1    = (const float*)d_in[15];
    const float* lin2_w = (const float*)d_in[16];
    const float* lin2_b = (const float*)d_in[17];
    const float* g2     = (const float*)d_in[18];
    const float* be2    = (const float*)d_in[19];
    const float* lin3_w = (const float*)d_in[20];
    const float* lin3_b = (const float*)d_in[21];
    const float* g3     = (const float*)d_in[22];
    const float* be3    = (const float*)d_in[23];
    const float* lin4_w = (const float*)d_in[24];
    const float* lin4_b = (const float*)d_in[25];
    float* out = (float*)d_out;

    void* pv;
    cudaGetSymbolAddress(&pv, g_cnt);  int*   cnt  = (int*)pv;
    cudaGetSymbolAddress(&pv, g_agg);  float* agg  = (float*)pv;
    cudaGetSymbolAddress(&pv, g_H);    float* H    = (float*)pv;
    cudaGetSymbolAddress(&pv, g_pool); float* pool = (float*)pv;
    cudaGetSymbolAddress(&pv, g_gcnt); int*   gcnt = (int*)pv;
    cudaGetSymbolAddress(&pv, g_c0);   float* c0   = (float*)pv;
    cudaGetSymbolAddress(&pv, g_t1);   float* t1   = (float*)pv;
    cudaGetSymbolAddress(&pv, g_t2);   float* t2   = (float*)pv;
    cudaGetSymbolAddress(&pv, g_t3);   float* t3   = (float*)pv;

    const int NB_NODE = N_NODES / 4;       // 12500 blocks for gemm_pr
    const int NV      = N_NODES * 64;      // 3.2M
    const int NE64    = N_EDGES * 64;      // 51.2M

    kdetect<<<1, 128>>>((const int*)ei);

    // degree counts -> inverse
    kzero_i<<<(N_NODES + 255) / 256, 256>>>(cnt, N_NODES);
    kcount<<<(N_EDGES + 255) / 256, 256>>>(ei);
    kinv<<<(N_NODES + 255) / 256, 256>>>();

    // ---- SAGE layer 1 (K=128) ----
    gemm_pr<128><<<NB_NODE, 128>>>(x, W1l, W1r);
    kzero_f<<<(NV + 255) / 256, 256>>>(agg, NV);
    kscatter<<<(NE64 + 255) / 256, 256>>>(ei);
    kcombine<<<(NV + 255) / 256, 256>>>(b1l);

    // ---- SAGE layer 2 (K=64) ----
    gemm_pr<64><<<NB_NODE, 128>>>(H, W2l, W2r);
    kzero_f<<<(NV + 255) / 256, 256>>>(agg, NV);
    kscatter<<<(NE64 + 255) / 256, 256>>>(ei);
    kcombine<<<(NV + 255) / 256, 256>>>(b2l);

    // ---- SAGE layer 3 (K=64) ----
    gemm_pr<64><<<NB_NODE, 128>>>(H, W3l, W3r);
    kzero_f<<<(NV + 255) / 256, 256>>>(agg, NV);
    kscatter<<<(NE64 + 255) / 256, 256>>>(ei);
    kcombine<<<(NV + 255) / 256, 256>>>(b3l);

    // ---- global mean pool ----
    kzero_f<<<(NG * 64 + 255) / 256, 256>>>(pool, NG * 64);
    kzero_i<<<1, 256>>>(gcnt, NG);
    kpool<<<(NV + 255) / 256, 256>>>(batch);
    kpooldiv<<<(NG * 64) / 256, 256>>>();

    // ---- MLP head ----
    gemm_rows<<<NG, 256, 256 * 4>>>(c0, lin1_w, lin1_b, t1, 64, 256);
    bn_tanh<<<256, 256>>>(t1, g1, be1, 256);
    gemm_rows<<<NG, 128, 256 * 4>>>(t1, lin2_w, lin2_b, t2, 256, 128);
    bn_tanh<<<128, 256>>>(t2, g2, be2, 128);
    gemm_rows<<<NG, 64, 128 * 4>>>(t2, lin3_w, lin3_b, t3, 128, 64);
    bn_tanh<<<64, 256>>>(t3, g3, be3, 64);
    gemm_rows<<<NG, 32, 64 * 4>>>(t3, lin4_w, lin4_b, out, 64, 10);
}

// round 6
// speedup vs baseline: 2.2766x; 2.2766x over previous
#include <cuda_runtime.h>

#define N_NODES 50000
#define N_EDGES 800000
#define NG 256

// ---------------- device scratch (no allocations allowed) ----------------
__device__ int    g_is64;
__device__ float4 g_PR4[N_NODES * 32];   // [P | R] per node, row = 128 floats = 32 float4
__device__ float4 g_H4[N_NODES * 16];    // node features, 64 floats = 16 float4
__device__ int    g_cnt[N_NODES];
__device__ int    g_cur[N_NODES];
__device__ int    g_rowstart[N_NODES + 1];
__device__ int    g_bsum[128];
__device__ int    g_csr[N_EDGES];
__device__ float  g_c0[NG * 64];
__device__ float  g_t1[NG * 256];
__device__ float  g_t2[NG * 128];
__device__ float  g_t3[NG * 64];

// index loader that works for int32 or int64 edge/batch arrays
__device__ __forceinline__ int ld_idx(const void* p, long long i) {
    return g_is64 ? (int)((const long long*)p)[i] : ((const int*)p)[i];
}

// ---------------- dtype detection ----------------
__global__ void kdetect(const int* ei32) {
    __shared__ int any;
    if (threadIdx.x == 0) any = 0;
    __syncthreads();
    if (ei32[2 * threadIdx.x + 1] != 0) atomicExch(&any, 1);
    __syncthreads();
    if (threadIdx.x == 0) g_is64 = (any == 0) ? 1 : 0;
}

// ---------------- zero cnt + cur ----------------
__global__ void kzero2() {
    int i = blockIdx.x * blockDim.x + threadIdx.x;
    if (i < N_NODES) { g_cnt[i] = 0; g_cur[i] = 0; }
}

// ---------------- degree counts ----------------
__global__ void kcount(const void* ei) {
    int e = blockIdx.x * blockDim.x + threadIdx.x;
    if (e < N_EDGES) {
        int d = ld_idx(ei, (long long)N_EDGES + e);
        atomicAdd(&g_cnt[d], 1);
    }
}

// ---------------- 3-kernel exclusive scan over cnt -> rowstart ----------------
__global__ void scan1() {
    __shared__ int sh[512];
    int i = blockIdx.x * 512 + threadIdx.x;
    int v = (i < N_NODES) ? g_cnt[i] : 0;
    sh[threadIdx.x] = v;
    __syncthreads();
    for (int o = 1; o < 512; o <<= 1) {
        int t = (threadIdx.x >= o) ? sh[threadIdx.x - o] : 0;
        __syncthreads();
        sh[threadIdx.x] += t;
        __syncthreads();
    }
    if (i < N_NODES) g_rowstart[i] = sh[threadIdx.x] - v;   // exclusive
    if (threadIdx.x == 511) g_bsum[blockIdx.x] = sh[511];
}
__global__ void scan2(int nb) {
    if (threadIdx.x == 0) {
        int run = 0;
        for (int b = 0; b < nb; b++) { int t = g_bsum[b]; g_bsum[b] = run; run += t; }
    }
}
__global__ void scan3() {
    int i = blockIdx.x * blockDim.x + threadIdx.x;
    if (i < N_NODES) g_rowstart[i] += g_bsum[i >> 9];
    if (i == 0) g_rowstart[N_NODES] = N_EDGES;
}

// ---------------- CSR fill ----------------
__global__ void kfill(const void* ei) {
    int e = blockIdx.x * blockDim.x + threadIdx.x;
    if (e < N_EDGES) {
        int s = ld_idx(ei, e);
        int d = ld_idx(ei, (long long)N_EDGES + e);
        int pos = g_rowstart[d] + atomicAdd(&g_cur[d], 1);
        g_csr[pos] = s;
    }
}

// ---------------- register-tiled GEMM: PR = [X@Wl | X@Wr] ----------------
// tile 64 rows x 128 cols, 256 threads, each thread 8 rows x 4 cols.
#define FMA4(A, s, B) { (A).x += (s)*(B).x; (A).y += (s)*(B).y; (A).z += (s)*(B).z; (A).w += (s)*(B).w; }

template <int K>
__global__ void gemm_pr2(const float* __restrict__ X,
                         const float* __restrict__ Wl,
                         const float* __restrict__ Wr) {
    __shared__ float4 XsT[32][16];   // [kk][row/4], 64 rows
    __shared__ float4 Ws[32][32];    // [kk][col/4], 128 cols
    int tid = threadIdx.x;
    int row0 = blockIdx.x * 64;
    int cg = tid & 31;   // col group (cols cg*4..cg*4+3)
    int rg = tid >> 5;   // 0..7 (rows rg*8..rg*8+7)
    int lr = tid >> 3;   // 0..31 loader row
    int lk4 = tid & 7;   // loader k-float4
    int wc = tid & 31;   // W loader col-float4
    int wk = tid >> 5;   // 0..7

    const float4* Wl4 = (const float4*)Wl;
    const float4* Wr4 = (const float4*)Wr;
    float* XsTf = (float*)XsT;

    float4 acc[8];
#pragma unroll
    for (int i = 0; i < 8; i++) acc[i] = make_float4(0.f, 0.f, 0.f, 0.f);

    for (int kc = 0; kc < K; kc += 32) {
        // load X chunk transposed: XsT[kk][r] = X[row0+r][kc+kk]
#pragma unroll
        for (int pass = 0; pass < 2; pass++) {
            int r = lr + pass * 32;
            float4 v = make_float4(0.f, 0.f, 0.f, 0.f);
            if (row0 + r < N_NODES)
                v = *(const float4*)(X + (long long)(row0 + r) * K + kc + lk4 * 4);
            XsTf[(lk4 * 4 + 0) * 64 + r] = v.x;
            XsTf[(lk4 * 4 + 1) * 64 + r] = v.y;
            XsTf[(lk4 * 4 + 2) * 64 + r] = v.z;
            XsTf[(lk4 * 4 + 3) * 64 + r] = v.w;
        }
        // load W chunk: Ws[kk][c4] = [Wl|Wr] row kc+kk
#pragma unroll
        for (int p = 0; p < 4; p++) {
            int kk = wk + p * 8;
            int k = kc + kk;
            Ws[kk][wc] = (wc < 16) ? Wl4[k * 16 + wc] : Wr4[k * 16 + (wc - 16)];
        }
        __syncthreads();

#pragma unroll 8
        for (int kk = 0; kk < 32; kk++) {
            float4 b = Ws[kk][cg];
            float4 a0 = XsT[kk][rg * 2];
            float4 a1 = XsT[kk][rg * 2 + 1];
            FMA4(acc[0], a0.x, b); FMA4(acc[1], a0.y, b);
            FMA4(acc[2], a0.z, b); FMA4(acc[3], a0.w, b);
            FMA4(acc[4], a1.x, b); FMA4(acc[5], a1.y, b);
            FMA4(acc[6], a1.z, b); FMA4(acc[7], a1.w, b);
        }
        __syncthreads();
    }
#pragma unroll
    for (int i = 0; i < 8; i++) {
        int row = row0 + rg * 8 + i;
        if (row < N_NODES) g_PR4[(long long)row * 32 + cg] = acc[i];
    }
}

// ---------------- CSR gather + combine: H = mean_aggr(P)[i] + bl + R[i] ----------------
// 16 threads per node, float4 per thread.
__global__ void kgather(const float* __restrict__ bl) {
    int t = blockIdx.x * blockDim.x + threadIdx.x;
    if (t >= N_NODES * 16) return;
    int node = t >> 4;
    int q = t & 15;
    int beg = g_rowstart[node];
    int end = g_rowstart[node + 1];
    float4 acc = make_float4(0.f, 0.f, 0.f, 0.f);
    int j = beg;
    for (; j + 4 <= end; j += 4) {
        int s0 = g_csr[j], s1 = g_csr[j + 1], s2 = g_csr[j + 2], s3 = g_csr[j + 3];
        float4 v0 = g_PR4[(long long)s0 * 32 + q];
        float4 v1 = g_PR4[(long long)s1 * 32 + q];
        float4 v2 = g_PR4[(long long)s2 * 32 + q];
        float4 v3 = g_PR4[(long long)s3 * 32 + q];
        acc.x += (v0.x + v1.x) + (v2.x + v3.x);
        acc.y += (v0.y + v1.y) + (v2.y + v3.y);
        acc.z += (v0.z + v1.z) + (v2.z + v3.z);
        acc.w += (v0.w + v1.w) + (v2.w + v3.w);
    }
    for (; j < end; j++) {
        int s = g_csr[j];
        float4 v = g_PR4[(long long)s * 32 + q];
        acc.x += v.x; acc.y += v.y; acc.z += v.z; acc.w += v.w;
    }
    float inv = 1.0f / fmaxf((float)(end - beg), 1.0f);
    float4 r = g_PR4[(long long)node * 32 + 16 + q];
    float4 b4 = ((const float4*)bl)[q];
    float4 h;
    h.x = acc.x * inv + b4.x + r.x;
    h.y = acc.y * inv + b4.y + r.y;
    h.z = acc.z * inv + b4.z + r.z;
    h.w = acc.w * inv + b4.w + r.w;
    g_H4[(long long)node * 16 + q] = h;
}

// ---------------- global mean pool (batch is sorted) ----------------
__global__ void kpool2(const void* batch) {
    int g = blockIdx.x;
    int c = threadIdx.x;  // 64 threads
    __shared__ int s_lo, s_hi;
    if (c < 2) {
        int target = g + c;   // lower_bound of target
        int lo = 0, hi = N_NODES;
        while (lo < hi) {
            int mid = (lo + hi) >> 1;
            if (ld_idx(batch, mid) < target) lo = mid + 1; else hi = mid;
        }
        if (c == 0) s_lo = lo; else s_hi = lo;
    }
    __syncthreads();
    int lo = s_lo, hi = s_hi;
    const float* H = (const float*)g_H4;
    float acc = 0.f;
    for (int i = lo; i < hi; i++) acc += H[(long long)i * 64 + c];
    int n = hi - lo;
    g_c0[g * 64 + c] = acc / fmaxf((float)n, 1.0f);
}

// ---------------- fused linear + batchnorm(train) + tanh ----------------
// grid = M (output cols), block = 256 (= NG rows)
__global__ void head_bn(const float* __restrict__ X, const float* __restrict__ W,
                        const float* __restrict__ b, const float* __restrict__ g,
                        const float* __restrict__ be, float* __restrict__ Y,
                        int K, int M) {
    int c = blockIdx.x;
    int r = threadIdx.x;
    float acc = b[c];
    const float* xr = X + r * K;
    for (int k = 0; k < K; k++) acc += xr[k] * W[k * M + c];
    __shared__ float red[256];
    __shared__ float stat;
    red[r] = acc;
    __syncthreads();
    for (int s = 128; s > 0; s >>= 1) {
        if (r < s) red[r] += red[r + s];
        __syncthreads();
    }
    if (r == 0) stat = red[0] * (1.0f / 256.0f);
    __syncthreads();
    float mean = stat;
    float d = acc - mean;
    __syncthreads();
    red[r] = d * d;
    __syncthreads();
    for (int s = 128; s > 0; s >>= 1) {
        if (r < s) red[r] += red[r + s];
        __syncthreads();
    }
    if (r == 0) stat = rsqrtf(red[0] * (1.0f / 256.0f) + 1e-5f);
    __syncthreads();
    Y[r * M + c] = tanhf(d * stat * g[c] + be[c]);
}

// ---------------- final small GEMM ----------------
__global__ void gemm_rows(const float* __restrict__ X, const float* __restrict__ W,
                          const float* __restrict__ b, float* __restrict__ Y,
                          int K, int M) {
    extern __shared__ float xs[];
    int row = blockIdx.x;
    int tid = threadIdx.x;
    for (int k = tid; k < K; k += blockDim.x) xs[k] = X[row * K + k];
    __syncthreads();
    if (tid < M) {
        float acc = b[tid];
        for (int k = 0; k < K; k++) acc += xs[k] * W[k * M + tid];
        Y[row * M + tid] = acc;
    }
}

// ---------------- host launch ----------------
extern "C" void kernel_launch(void* const* d_in, const int* in_sizes, int n_in,
                              void* d_out, int out_size) {
    const float* x      = (const float*)d_in[0];
    const void*  ei     = d_in[1];
    const void*  batch  = d_in[2];
    const float* W1l    = (const float*)d_in[3];
    const float* b1l    = (const float*)d_in[4];
    const float* W1r    = (const float*)d_in[5];
    const float* W2l    = (const float*)d_in[6];
    const float* b2l    = (const float*)d_in[7];
    const float* W2r    = (const float*)d_in[8];
    const float* W3l    = (const float*)d_in[9];
    const float* b3l    = (const float*)d_in[10];
    const float* W3r    = (const float*)d_in[11];
    const float* lin1_w = (const float*)d_in[12];
    const float* lin1_b = (const float*)d_in[13];
    const float* g1     = (const float*)d_in[14];
    const float* be1    = (const float*)d_in[15];
    const float* lin2_w = (const float*)d_in[16];
    const float* lin2_b = (const float*)d_in[17];
    const float* g2     = (const float*)d_in[18];
    const float* be2    = (const float*)d_in[19];
    const float* lin3_w = (const float*)d_in[20];
    const float* lin3_b = (const float*)d_in[21];
    const float* g3     = (const float*)d_in[22];
    const float* be3    = (const float*)d_in[23];
    const float* lin4_w = (const float*)d_in[24];
    const float* lin4_b = (const float*)d_in[25];
    float* out = (float*)d_out;

    void* pv;
    cudaGetSymbolAddress(&pv, g_H4);  const float* Hf = (const float*)pv;
    cudaGetSymbolAddress(&pv, g_c0);  float* c0 = (float*)pv;
    cudaGetSymbolAddress(&pv, g_t1);  float* t1 = (float*)pv;
    cudaGetSymbolAddress(&pv, g_t2);  float* t2 = (float*)pv;
    cudaGetSymbolAddress(&pv, g_t3);  float* t3 = (float*)pv;

    const int NB_GEMM = (N_NODES + 63) / 64;           // 782
    const int NB_GATH = (N_NODES * 16 + 255) / 256;    // 3125
    const int NB_SCAN = (N_NODES + 511) / 512;         // 98

    kdetect<<<1, 128>>>((const int*)ei);

    // ---- CSR build (reused by all 3 layers) ----
    kzero2<<<(N_NODES + 255) / 256, 256>>>();
    kcount<<<(N_EDGES + 255) / 256, 256>>>(ei);
    scan1<<<NB_SCAN, 512>>>();
    scan2<<<1, 32>>>(NB_SCAN);
    scan3<<<(N_NODES + 255) / 256, 256>>>();
    kfill<<<(N_EDGES + 255) / 256, 256>>>(ei);

    // ---- SAGE layer 1 (K=128) ----
    gemm_pr2<128><<<NB_GEMM, 256>>>(x, W1l, W1r);
    kgather<<<NB_GATH, 256>>>(b1l);

    // ---- SAGE layer 2 (K=64) ----
    gemm_pr2<64><<<NB_GEMM, 256>>>(Hf, W2l, W2r);
    kgather<<<NB_GATH, 256>>>(b2l);

    // ---- SAGE layer 3 (K=64) ----
    gemm_pr2<64><<<NB_GEMM, 256>>>(Hf, W3l, W3r);
    kgather<<<NB_GATH, 256>>>(b3l);

    // ---- global mean pool ----
    kpool2<<<NG, 64>>>(batch);

    // ---- MLP head (fused gemm+BN+tanh per column) ----
    head_bn<<<256, 256>>>(c0, lin1_w, lin1_b, g1, be1, t1, 64, 256);
    head_bn<<<128, 256>>>(t1, lin2_w, lin2_b, g2, be2, t2, 256, 128);
    head_bn<<<64, 256>>>(t2, lin3_w, lin3_b, g3, be3, t3, 128, 64);
    gemm_rows<<<NG, 64, 64 * 4>>>(t3, lin4_w, lin4_b, out, 64, 10);
}